// round 7
// baseline (speedup 1.0000x reference)
#include <cuda_runtime.h>
#include <cuda_bf16.h>
#include <cstdint>

#define B_   32
#define S_   512
#define I_   512
#define H_   512
#define G4_  2048   // 4*H

#define SH_OFF   16777216u            // stacked_h offset in out
#define SC_OFF   (16777216u + 32768u) // stacked_c offset in out

#define RSTR 520                      // bf16 smem row stride (conflict-free ldmatrix)

// ---------------- device scratch (allocations are forbidden) ----------------
__device__ __align__(16) float g_pre[(size_t)2 * S_ * B_ * G4_]; // [dir][t][b][4H]
__device__ __align__(16) __nv_bfloat16 g_hHi[2][2][B_ * H_];     // h hi plane
__device__ __align__(16) __nv_bfloat16 g_hLo[2][2][B_ * H_];     // h lo plane
__device__ unsigned int g_bar[2];

// bf16 hi/lo splits (written by prep_kernel)
__device__ __align__(16) __nv_bfloat16 g_Xhi[8388608];
__device__ __align__(16) __nv_bfloat16 g_Xlo[8388608];
__device__ __align__(16) __nv_bfloat16 g_Whi[2097152];  // Wih  [dir][2048][512]
__device__ __align__(16) __nv_bfloat16 g_Wlo[2097152];
__device__ __align__(16) __nv_bfloat16 g_Uhi[2097152];  // Whh  [dir][2048][512]
__device__ __align__(16) __nv_bfloat16 g_Ulo[2097152];

// ---------------- init ----------------
__global__ void init_kernel() {
    int idx = blockIdx.x * blockDim.x + threadIdx.x;
    if (idx < 32768) {
        ((uint32_t*)g_hHi)[idx] = 0u;
        ((uint32_t*)g_hLo)[idx] = 0u;
    }
    if (idx < 2) g_bar[idx] = 0u;
}

// ---------------- prep: split fp32 -> bf16 hi + lo ----------------
__device__ __forceinline__ void split2(float x, __nv_bfloat16& h, __nv_bfloat16& l) {
    h = __float2bfloat16(x);
    l = __float2bfloat16(x - __bfloat162float(h));
}

__global__ __launch_bounds__(256) void prep_kernel(
    const float* __restrict__ X,
    const float* __restrict__ Wf, const float* __restrict__ Wb,
    const float* __restrict__ Uf, const float* __restrict__ Ub)
{
    const int NXv = 8388608 / 4;
    const int NWv = 1048576 / 4;
    int i = blockIdx.x * 256 + threadIdx.x;

    const float* src;
    __nv_bfloat16 *dh, *dl;
    int o;
    if (i < NXv)                 { src = X;  dh = g_Xhi;           dl = g_Xlo;           o = i; }
    else if (i < NXv + NWv)      { src = Wf; dh = g_Whi;           dl = g_Wlo;           o = i - NXv; }
    else if (i < NXv + 2 * NWv)  { src = Wb; dh = g_Whi + 1048576; dl = g_Wlo + 1048576; o = i - NXv - NWv; }
    else if (i < NXv + 3 * NWv)  { src = Uf; dh = g_Uhi;           dl = g_Ulo;           o = i - NXv - 2 * NWv; }
    else if (i < NXv + 4 * NWv)  { src = Ub; dh = g_Uhi + 1048576; dl = g_Ulo + 1048576; o = i - NXv - 3 * NWv; }
    else return;

    float4 v = ((const float4*)src)[o];
    __nv_bfloat16 h0, l0, h1, l1, h2, l2, h3, l3;
    split2(v.x, h0, l0); split2(v.y, h1, l1);
    split2(v.z, h2, l2); split2(v.w, h3, l3);
    ((__nv_bfloat162*)dh)[2 * o]     = __nv_bfloat162{h0, h1};
    ((__nv_bfloat162*)dh)[2 * o + 1] = __nv_bfloat162{h2, h3};
    ((__nv_bfloat162*)dl)[2 * o]     = __nv_bfloat162{l0, l1};
    ((__nv_bfloat162*)dl)[2 * o + 1] = __nv_bfloat162{l2, l3};
}

// ---------------- tensor-core helpers ----------------
__device__ __forceinline__ void mma16816(float* c, const uint32_t* a, const uint32_t* b) {
    asm volatile(
        "mma.sync.aligned.m16n8k16.row.col.f32.bf16.bf16.f32 "
        "{%0,%1,%2,%3}, {%4,%5,%6,%7}, {%8,%9}, {%0,%1,%2,%3};"
        : "+f"(c[0]), "+f"(c[1]), "+f"(c[2]), "+f"(c[3])
        : "r"(a[0]), "r"(a[1]), "r"(a[2]), "r"(a[3]), "r"(b[0]), "r"(b[1]));
}
__device__ __forceinline__ void ldsm_x4(uint32_t* r, uint32_t addr) {
    asm volatile("ldmatrix.sync.aligned.m8n8.x4.shared.b16 {%0,%1,%2,%3}, [%4];"
                 : "=r"(r[0]), "=r"(r[1]), "=r"(r[2]), "=r"(r[3]) : "r"(addr));
}
__device__ __forceinline__ void ldsm_x2(uint32_t* r, uint32_t addr) {
    asm volatile("ldmatrix.sync.aligned.m8n8.x2.shared.b16 {%0,%1}, [%2];"
                 : "=r"(r[0]), "=r"(r[1]) : "r"(addr));
}
__device__ __forceinline__ void cpasync16(uint32_t dst, const void* src) {
    asm volatile("cp.async.cg.shared.global [%0], [%1], 16;" :: "r"(dst), "l"(src));
}
#define CP_COMMIT() asm volatile("cp.async.commit_group;")

// ---------------- phase 1: G = X @ Wih^T + (bih+bhh) ----------------
// CTA tile 128x128, K-tile 32, double-buffered cp.async, 2 CTAs/SM.
// buffer: Ahi@0 Alo@10240 Bhi@20480 Blo@30720 (bf16 [128][40]); buf stride 40960
__global__ __launch_bounds__(256, 2) void xgemm_mma(
    const float* __restrict__ bih_f, const float* __restrict__ bhh_f,
    const float* __restrict__ bih_b, const float* __restrict__ bhh_b)
{
    extern __shared__ __nv_bfloat16 smem_bf[];
    const uint32_t smb = (uint32_t)__cvta_generic_to_shared(smem_bf);

    const int tid  = threadIdx.x;
    const int lane = tid & 31;
    const int warp = tid >> 5;
    const int d     = blockIdx.z;
    const int m_blk = blockIdx.y * 128;
    const int n_blk = blockIdx.x * 128;
    const int wm = (warp >> 2) * 64;
    const int wn = (warp & 3) * 32;

    const size_t wofs = (size_t)d * 1048576;

    float acc[4][4][4];
#pragma unroll
    for (int i = 0; i < 4; i++)
#pragma unroll
        for (int j = 0; j < 4; j++)
#pragma unroll
            for (int c = 0; c < 4; c++) acc[i][j][c] = 0.0f;

    const int lrow = tid >> 2;        // 0..63
    const int loff = (tid & 3) << 3;  // 0,8,16,24

    auto load_tile = [&](int kt, int buf) {
        uint32_t base = smb + (uint32_t)buf * 40960u;
#pragma unroll
        for (int p = 0; p < 2; p++) {
            int row = lrow + p * 64;
            uint32_t doff = (uint32_t)(row * 40 + loff) * 2u;
            int m = m_blk + row;
            int bb = m & 31, tt = m >> 5;
            size_t aoff = (((size_t)bb * 512 + tt) << 9) + kt + loff;
            cpasync16(base + doff,          g_Xhi + aoff);
            cpasync16(base + 10240u + doff, g_Xlo + aoff);
            size_t boff = wofs + ((size_t)(n_blk + row) << 9) + kt + loff;
            cpasync16(base + 20480u + doff, g_Whi + boff);
            cpasync16(base + 30720u + doff, g_Wlo + boff);
        }
    };

    load_tile(0, 0);
    CP_COMMIT();

    int buf = 0;
    for (int it = 0; it < 16; it++) {
        if (it < 15) { load_tile((it + 1) * 32, buf ^ 1); CP_COMMIT(); }
        if (it < 15) asm volatile("cp.async.wait_group 1;");
        else         asm volatile("cp.async.wait_group 0;");
        __syncthreads();

        uint32_t bufb = smb + (uint32_t)buf * 40960u;
        const int l = lane & 15;
#pragma unroll
        for (int kf = 0; kf < 32; kf += 16) {
            uint32_t bh[4][2], bl[4][2];
            uint32_t brel = (uint32_t)(((wn + (l & 7)) * 40 + kf + ((l >> 3) << 3)) * 2);
#pragma unroll
            for (int fn = 0; fn < 4; fn++) {
                uint32_t ad = bufb + 20480u + brel + (uint32_t)(fn * 8 * 40 * 2);
                ldsm_x2(bh[fn], ad);
                ldsm_x2(bl[fn], ad + 10240u);
            }
            uint32_t arel = (uint32_t)(((wm + l) * 40 + kf + ((lane >> 4) << 3)) * 2);
#pragma unroll
            for (int fm = 0; fm < 4; fm++) {
                uint32_t aa = bufb + arel + (uint32_t)(fm * 16 * 40 * 2);
                uint32_t ah[4], al[4];
                ldsm_x4(ah, aa);
                ldsm_x4(al, aa + 10240u);
#pragma unroll
                for (int fn = 0; fn < 4; fn++) {
                    mma16816(acc[fm][fn], ah, bh[fn]);
                    mma16816(acc[fm][fn], ah, bl[fn]);
                    mma16816(acc[fm][fn], al, bh[fn]);
                }
            }
        }
        __syncthreads();
        buf ^= 1;
    }

    const float* bi  = d ? bih_b : bih_f;
    const float* bhp = d ? bhh_b : bhh_f;
#pragma unroll
    for (int fn = 0; fn < 4; fn++) {
        int n = n_blk + wn + fn * 8 + ((lane & 3) << 1);
        float b0 = bi[n] + bhp[n];
        float b1 = bi[n + 1] + bhp[n + 1];
#pragma unroll
        for (int fm = 0; fm < 4; fm++) {
            int m = m_blk + wm + fm * 16 + (lane >> 2);
            int t0 = m >> 5, bb0 = m & 31;
            float2 v0 = make_float2(acc[fm][fn][0] + b0, acc[fm][fn][1] + b1);
            *(float2*)(g_pre + ((((size_t)d * 512 + t0) * 32 + bb0) << 11) + n) = v0;
            int m2 = m + 8;
            int t1 = m2 >> 5, bb1 = m2 & 31;
            float2 v1 = make_float2(acc[fm][fn][2] + b0, acc[fm][fn][3] + b1);
            *(float2*)(g_pre + ((((size_t)d * 512 + t1) * 32 + bb1) << 11) + n) = v1;
        }
    }
}

// ---------------- activations (fp32, ~2^-21 rel err) ----------------
__device__ __forceinline__ float sigm_(float x) {
    x = fminf(fmaxf(x, -30.0f), 30.0f);
    return __fdividef(1.0f, 1.0f + __expf(-x));
}
__device__ __forceinline__ float tanh_(float x) {
    x = fminf(fmaxf(x, -15.0f), 15.0f);
    float e = __expf(-2.0f * x);
    return __fdividef(1.0f - e, 1.0f + e);
}

// ---------------- phase 2: persistent recurrence (tensor core) ----------------
// grid (64, 2). CTA owns 8 hidden units (32 gate rows).
// smem: Whi[32][520], Wlo, hHi[32][520], hLo (bf16) + gates[32][33] f32
__global__ __launch_bounds__(256, 1) void recur_kernel(float* __restrict__ out)
{
    extern __shared__ __nv_bfloat16 smr[];
    float* gatesS = (float*)(smr + 4 * 32 * RSTR);  // [32][33]

    const int tid  = threadIdx.x;
    const int lane = tid & 31;
    const int warp = tid >> 5;
    const int q = blockIdx.x;          // 0..63
    const int d = blockIdx.y;          // 0..1
    const int j0 = q << 3;

    // one-time: load this CTA's Whh slice (hi/lo) into smem
    {
        __nv_bfloat16* WhiS = smr;
        __nv_bfloat16* WloS = smr + 32 * RSTR;
        const __nv_bfloat16* Uh = g_Uhi + (size_t)d * 1048576;
        const __nv_bfloat16* Ul = g_Ulo + (size_t)d * 1048576;
        for (int e = tid; e < 4096; e += 256) {
            int r = e >> 7;
            int k = (e & 127) << 2;
            int grow = ((r >> 3) << 9) + j0 + (r & 7);
            size_t so = (size_t)grow * 512 + k;
            *(uint2*)&WhiS[r * RSTR + k] = *(const uint2*)(Uh + so);
            *(uint2*)&WloS[r * RSTR + k] = *(const uint2*)(Ul + so);
        }
    }

    const uint32_t smb  = (uint32_t)__cvta_generic_to_shared(smr);
    const uint32_t WhiA = smb;
    const uint32_t WloA = smb + 32 * RSTR * 2;
    const uint32_t hHiA = smb + 2 * 32 * RSTR * 2;
    const uint32_t hLoA = smb + 3 * 32 * RSTR * 2;

    // warp MMA footprint: C tile [16 x 8] at (m0, n0)
    const int m0 = (warp & 1) << 4;
    const int n0 = (warp >> 1) << 3;
    const uint32_t aRel  = (uint32_t)(((m0 + (lane & 15)) * RSTR + ((lane >> 4) << 3)) * 2);
    const uint32_t bRel4 = (uint32_t)(((n0 + (lane & 7)) * RSTR + ((lane >> 3) << 3)) * 2);

    // cell ownership: (b, j)
    const int ab = tid >> 3, ajl = tid & 7;
    float c_reg = 0.0f;

    for (int s = 0; s < S_; s++) {
        const int t = d ? (S_ - 1 - s) : s;

        // 1. async-load h hi/lo planes into smem
        const __nv_bfloat16* hi_src = g_hHi[d][s & 1];
        const __nv_bfloat16* lo_src = g_hLo[d][s & 1];
#pragma unroll
        for (int i = 0; i < 8; i++) {
            int c = tid + (i << 8);          // 0..2047
            int b = c >> 6, k = (c & 63) << 3;
            uint32_t doff = (uint32_t)(b * RSTR + k) * 2u;
            size_t so = (size_t)(b << 9) + k;
            cpasync16(hHiA + doff, hi_src + so);
            cpasync16(hLoA + doff, lo_src + so);
        }
        CP_COMMIT();

        // prefetch this step's pre-activations (overlaps cp.async)
        const float* gpt = g_pre + (((size_t)(d * S_ + t) * B_ + ab) << 11) + j0 + ajl;
        float gp0 = __ldg(gpt);
        float gp1 = __ldg(gpt + 512);
        float gp2 = __ldg(gpt + 1024);
        float gp3 = __ldg(gpt + 1536);

        asm volatile("cp.async.wait_group 0;");
        __syncthreads();

        // 2. split-bf16 tensor GEMM (B frags via x4 double-k)
        float c4[4] = {0.f, 0.f, 0.f, 0.f};
#pragma unroll 4
        for (int ks = 0; ks < 16; ks++) {       // 32 k per iter
            uint32_t ko = (uint32_t)(ks << 6);  // 32 bf16 * 2B
            uint32_t bh[4], bl[4];
            ldsm_x4(bh, WhiA + bRel4 + ko);
            ldsm_x4(bl, WloA + bRel4 + ko);
            uint32_t ah0[4], al0[4], ah1[4], al1[4];
            ldsm_x4(ah0, hHiA + aRel + ko);
            ldsm_x4(al0, hLoA + aRel + ko);
            ldsm_x4(ah1, hHiA + aRel + ko + 32);
            ldsm_x4(al1, hLoA + aRel + ko + 32);
            mma16816(c4, ah0, bh);
            mma16816(c4, ah0, bl);
            mma16816(c4, al0, bh);
            mma16816(c4, ah1, bh + 2);
            mma16816(c4, ah1, bl + 2);
            mma16816(c4, al1, bh + 2);
        }

        // 3. frags -> smem gates
        {
            int row = m0 + (lane >> 2);
            int col = n0 + ((lane & 3) << 1);
            gatesS[row * 33 + col]           = c4[0];
            gatesS[row * 33 + col + 1]       = c4[1];
            gatesS[(row + 8) * 33 + col]     = c4[2];
            gatesS[(row + 8) * 33 + col + 1] = c4[3];
        }
        __syncthreads();

        // 4. LSTM cell update; write h hi/lo planes
        float h_val, c_new;
        {
            const float* gb = gatesS + ab * 33;
            float i_s = sigm_(gb[ajl]      + gp0);
            float f_s = sigm_(gb[8 + ajl]  + gp1);
            float g_t = tanh_(gb[16 + ajl] + gp2);
            float o_s = sigm_(gb[24 + ajl] + gp3);
            c_new = f_s * c_reg + i_s * g_t;
            c_reg = c_new;
            h_val = o_s * tanh_(c_new);

            __nv_bfloat16 hh = __float2bfloat16(h_val);
            __nv_bfloat16 hl = __float2bfloat16(h_val - __bfloat162float(hh));
            int idx = (ab << 9) + j0 + ajl;
            g_hHi[d][(s + 1) & 1][idx] = hh;
            g_hLo[d][(s + 1) & 1][idx] = hl;
        }
        __syncthreads();   // h-plane stores issued by all threads

        // 5. arrive early, overlap out[] store with other CTAs' arrivals
        if (tid == 0) {
            __threadfence();
            atomicAdd(&g_bar[d], 1u);
        }

        out[((size_t)(ab * S_ + t) << 10) + (d << 9) + j0 + ajl] = h_val;
        if (s == S_ - 1) {
            size_t fo = (size_t)(d * B_ + ab) * H_ + j0 + ajl;
            out[SH_OFF + fo] = h_val;
            out[SC_OFF + fo] = c_reg;
        }

        if (tid == 0) {
            unsigned int target = 64u * (unsigned)(s + 1);
            volatile unsigned int* p = &g_bar[d];
            while (*p < target) __nanosleep(32);
            __threadfence();
        }
        __syncthreads();
    }
}

// ---------------- launch ----------------
extern "C" void kernel_launch(void* const* d_in, const int* in_sizes, int n_in,
                              void* d_out, int out_size) {
    const float* X     = (const float*)d_in[0];
    const float* Wih_f = (const float*)d_in[1];
    const float* Whh_f = (const float*)d_in[2];
    const float* bih_f = (const float*)d_in[3];
    const float* bhh_f = (const float*)d_in[4];
    const float* Wih_b = (const float*)d_in[5];
    const float* Whh_b = (const float*)d_in[6];
    const float* bih_b = (const float*)d_in[7];
    const float* bhh_b = (const float*)d_in[8];
    float* out = (float*)d_out;

    static const size_t rec_sh = (size_t)(4 * 32 * RSTR) * 2 + 32 * 33 * 4; // 137344
    static const size_t gem_sh = 2 * 40960;                                  // 81920
    cudaFuncSetAttribute(recur_kernel, cudaFuncAttributeMaxDynamicSharedMemorySize, (int)rec_sh);
    cudaFuncSetAttribute(xgemm_mma,    cudaFuncAttributeMaxDynamicSharedMemorySize, (int)gem_sh);

    init_kernel<<<(32768 + 255) / 256, 256>>>();
    prep_kernel<<<(2097152 + 4 * 262144 + 255) / 256, 256>>>(X, Wih_f, Wih_b, Whh_f, Whh_b);
    xgemm_mma<<<dim3(G4_ / 128, (B_ * S_) / 128, 2), 256, gem_sh>>>(bih_f, bhh_f, bih_b, bhh_b);
    recur_kernel<<<dim3(64, 2), 256, rec_sh>>>(out);
}

// round 11
// speedup vs baseline: 1.2014x; 1.2014x over previous
#include <cuda_runtime.h>
#include <cuda_bf16.h>
#include <cstdint>

#define B_   32
#define S_   512
#define I_   512
#define H_   512
#define G4_  2048   // 4*H

#define SH_OFF   16777216u            // stacked_h offset in out
#define SC_OFF   (16777216u + 32768u) // stacked_c offset in out

#define RSTR 520                      // bf16 smem row stride (conflict-free ldmatrix)

// xgemm smem layout (bf16 elems unless noted), per stage (bytes):
//   Ahi @ 0      : 128 rows x 72 cols  = 18432 B
//   Alo @ 18432  : 128 x 72            = 18432 B
//   Bhi @ 36864  :  64 x 72            =  9216 B
//   Blo @ 46080  :  64 x 72            =  9216 B
//   stage stride 55296 B, 2 stages = 110592 B  -> 2 CTAs/SM
#define XST 55296u

// ---------------- device scratch (allocations are forbidden) ----------------
__device__ __align__(16) float    g_pre[(size_t)2 * S_ * B_ * G4_]; // [dir][t][b][4H]
__device__ __align__(16) uint32_t g_hpk[2][2][B_ * H_];             // packed bf16 (hi|lo<<16)
__device__ unsigned int           g_bar[2];

// bf16 hi/lo splits (written by prep_kernel)
__device__ __align__(16) __nv_bfloat16 g_Xhi[8388608];
__device__ __align__(16) __nv_bfloat16 g_Xlo[8388608];
__device__ __align__(16) __nv_bfloat16 g_Whi[2097152];  // Wih  [dir][2048][512]
__device__ __align__(16) __nv_bfloat16 g_Wlo[2097152];
__device__ __align__(16) __nv_bfloat16 g_Uhi[2097152];  // Whh  [dir][2048][512]
__device__ __align__(16) __nv_bfloat16 g_Ulo[2097152];

// ---------------- init ----------------
__global__ void init_kernel() {
    int idx = blockIdx.x * blockDim.x + threadIdx.x;
    if (idx < 2 * 2 * B_ * H_) ((uint32_t*)g_hpk)[idx] = 0u;
    if (idx < 2) g_bar[idx] = 0u;
}

// ---------------- prep: split fp32 -> bf16 hi + lo ----------------
__device__ __forceinline__ void split2(float x, __nv_bfloat16& h, __nv_bfloat16& l) {
    h = __float2bfloat16(x);
    l = __float2bfloat16(x - __bfloat162float(h));
}

__global__ __launch_bounds__(256) void prep_kernel(
    const float* __restrict__ X,
    const float* __restrict__ Wf, const float* __restrict__ Wb,
    const float* __restrict__ Uf, const float* __restrict__ Ub)
{
    const int NXv = 8388608 / 4;
    const int NWv = 1048576 / 4;
    int i = blockIdx.x * 256 + threadIdx.x;

    const float* src;
    __nv_bfloat16 *dh, *dl;
    int o;
    if (i < NXv)                 { src = X;  dh = g_Xhi;           dl = g_Xlo;           o = i; }
    else if (i < NXv + NWv)      { src = Wf; dh = g_Whi;           dl = g_Wlo;           o = i - NXv; }
    else if (i < NXv + 2 * NWv)  { src = Wb; dh = g_Whi + 1048576; dl = g_Wlo + 1048576; o = i - NXv - NWv; }
    else if (i < NXv + 3 * NWv)  { src = Uf; dh = g_Uhi;           dl = g_Ulo;           o = i - NXv - 2 * NWv; }
    else if (i < NXv + 4 * NWv)  { src = Ub; dh = g_Uhi + 1048576; dl = g_Ulo + 1048576; o = i - NXv - 3 * NWv; }
    else return;

    float4 v = ((const float4*)src)[o];
    __nv_bfloat16 h0, l0, h1, l1, h2, l2, h3, l3;
    split2(v.x, h0, l0); split2(v.y, h1, l1);
    split2(v.z, h2, l2); split2(v.w, h3, l3);
    ((__nv_bfloat162*)dh)[2 * o]     = __nv_bfloat162{h0, h1};
    ((__nv_bfloat162*)dh)[2 * o + 1] = __nv_bfloat162{h2, h3};
    ((__nv_bfloat162*)dl)[2 * o]     = __nv_bfloat162{l0, l1};
    ((__nv_bfloat162*)dl)[2 * o + 1] = __nv_bfloat162{l2, l3};
}

// ---------------- tensor-core helpers (mma.sync path only; no tcgen05 on this toolchain) ----
__device__ __forceinline__ void mma16816(float* c, const uint32_t* a, const uint32_t* b) {
    asm volatile(
        "mma.sync.aligned.m16n8k16.row.col.f32.bf16.bf16.f32 "
        "{%0,%1,%2,%3}, {%4,%5,%6,%7}, {%8,%9}, {%0,%1,%2,%3};"
        : "+f"(c[0]), "+f"(c[1]), "+f"(c[2]), "+f"(c[3])
        : "r"(a[0]), "r"(a[1]), "r"(a[2]), "r"(a[3]), "r"(b[0]), "r"(b[1]));
}
__device__ __forceinline__ void ldsm_x4(uint32_t* r, uint32_t addr) {
    asm volatile("ldmatrix.sync.aligned.m8n8.x4.shared.b16 {%0,%1,%2,%3}, [%4];"
                 : "=r"(r[0]), "=r"(r[1]), "=r"(r[2]), "=r"(r[3]) : "r"(addr));
}
__device__ __forceinline__ void ldsm_x2(uint32_t* r, uint32_t addr) {
    asm volatile("ldmatrix.sync.aligned.m8n8.x2.shared.b16 {%0,%1}, [%2];"
                 : "=r"(r[0]), "=r"(r[1]) : "r"(addr));
}
__device__ __forceinline__ void cpasync16(uint32_t dst, const void* src) {
    asm volatile("cp.async.cg.shared.global [%0], [%1], 16;" :: "r"(dst), "l"(src));
}
#define CP_COMMIT() asm volatile("cp.async.commit_group;")

// ---------------- phase 1: G = X @ Wih^T + (bih+bhh) ----------------
// CTA tile 128(m) x 64(n), K-tile 64, double-buffered cp.async, 2 CTAs/SM.
// 8 warps: 4 in m (32 rows each) x 2 in n (32 cols each); warp microtile 32x32.
__global__ __launch_bounds__(256, 2) void xgemm_mma(
    const float* __restrict__ bih_f, const float* __restrict__ bhh_f,
    const float* __restrict__ bih_b, const float* __restrict__ bhh_b)
{
    extern __shared__ __nv_bfloat16 smem_bf[];
    const uint32_t smb = (uint32_t)__cvta_generic_to_shared(smem_bf);

    const int tid  = threadIdx.x;
    const int lane = tid & 31;
    const int warp = tid >> 5;
    const int d     = blockIdx.z;
    const int m_blk = blockIdx.y * 128;
    const int n_blk = blockIdx.x * 64;
    const int wm = (warp & 3) * 32;    // 4 warps in m
    const int wn = (warp >> 2) * 32;   // 2 warps in n

    const size_t wofs = (size_t)d * 1048576;

    float acc[2][4][4];
#pragma unroll
    for (int i = 0; i < 2; i++)
#pragma unroll
        for (int j = 0; j < 4; j++)
#pragma unroll
            for (int c = 0; c < 4; c++) acc[i][j][c] = 0.0f;

    // loader: 3072 16B-chunks per stage, 12 per thread
    auto load_tile = [&](int kt, int buf) {
        uint32_t base = smb + (uint32_t)buf * XST;
#pragma unroll
        for (int i = 0; i < 12; i++) {
            int c = tid + (i << 8);            // 0..3071
            if (c < 2048) {                    // A planes
                int plane = c >> 10;           // 0 = hi, 1 = lo
                int cc    = c & 1023;
                int row   = cc >> 3;
                int colc  = (cc & 7) << 3;
                uint32_t dst = base + (uint32_t)plane * 18432u +
                               (uint32_t)(row * 72 + colc) * 2u;
                int m = m_blk + row;
                size_t aoff = (((size_t)(m & 31) * 512 + (m >> 5)) << 9) + kt + colc;
                cpasync16(dst, (plane ? g_Xlo : g_Xhi) + aoff);
            } else {                           // B planes
                int cc    = c - 2048;          // 0..1023
                int plane = cc >> 9;           // 0 = hi, 1 = lo
                int c2    = cc & 511;
                int row   = c2 >> 3;
                int colc  = (c2 & 7) << 3;
                uint32_t dst = base + 36864u + (uint32_t)plane * 9216u +
                               (uint32_t)(row * 72 + colc) * 2u;
                size_t boff = wofs + ((size_t)(n_blk + row) << 9) + kt + colc;
                cpasync16(dst, (plane ? g_Wlo : g_Whi) + boff);
            }
        }
    };

    load_tile(0, 0);
    CP_COMMIT();

    int buf = 0;
    for (int it = 0; it < 8; it++) {
        if (it < 7) { load_tile((it + 1) * 64, buf ^ 1); CP_COMMIT(); }
        if (it < 7) asm volatile("cp.async.wait_group 1;");
        else        asm volatile("cp.async.wait_group 0;");
        __syncthreads();

        uint32_t bufb = smb + (uint32_t)buf * XST;
        const int l = lane & 15;
#pragma unroll
        for (int kf = 0; kf < 64; kf += 16) {
            uint32_t bh[4][2], bl[4][2];
            uint32_t brel = (uint32_t)(((wn + (l & 7)) * 72 + kf + ((l >> 3) << 3)) * 2);
#pragma unroll
            for (int fn = 0; fn < 4; fn++) {
                uint32_t ad = bufb + 36864u + brel + (uint32_t)(fn * 8 * 72 * 2);
                ldsm_x2(bh[fn], ad);
                ldsm_x2(bl[fn], ad + 9216u);
            }
            uint32_t arel = (uint32_t)(((wm + l) * 72 + kf + ((lane >> 4) << 3)) * 2);
#pragma unroll
            for (int fm = 0; fm < 2; fm++) {
                uint32_t aa = bufb + arel + (uint32_t)(fm * 16 * 72 * 2);
                uint32_t ah[4], al[4];
                ldsm_x4(ah, aa);
                ldsm_x4(al, aa + 18432u);
#pragma unroll
                for (int fn = 0; fn < 4; fn++) {
                    mma16816(acc[fm][fn], ah, bh[fn]);
                    mma16816(acc[fm][fn], ah, bl[fn]);
                    mma16816(acc[fm][fn], al, bh[fn]);
                }
            }
        }
        __syncthreads();
        buf ^= 1;
    }

    const float* bi  = d ? bih_b : bih_f;
    const float* bhp = d ? bhh_b : bhh_f;
#pragma unroll
    for (int fn = 0; fn < 4; fn++) {
        int n = n_blk + wn + fn * 8 + ((lane & 3) << 1);
        float b0 = bi[n] + bhp[n];
        float b1 = bi[n + 1] + bhp[n + 1];
#pragma unroll
        for (int fm = 0; fm < 2; fm++) {
            int m = m_blk + wm + fm * 16 + (lane >> 2);
            int t0 = m >> 5, bb0 = m & 31;
            float2 v0 = make_float2(acc[fm][fn][0] + b0, acc[fm][fn][1] + b1);
            *(float2*)(g_pre + ((((size_t)d * 512 + t0) * 32 + bb0) << 11) + n) = v0;
            int m2 = m + 8;
            int t1 = m2 >> 5, bb1 = m2 & 31;
            float2 v1 = make_float2(acc[fm][fn][2] + b0, acc[fm][fn][3] + b1);
            *(float2*)(g_pre + ((((size_t)d * 512 + t1) * 32 + bb1) << 11) + n) = v1;
        }
    }
}

// ---------------- activations (fp32, ~2^-21 rel err) ----------------
__device__ __forceinline__ float sigm_(float x) {
    x = fminf(fmaxf(x, -30.0f), 30.0f);
    return __fdividef(1.0f, 1.0f + __expf(-x));
}
__device__ __forceinline__ float tanh_(float x) {
    x = fminf(fmaxf(x, -15.0f), 15.0f);
    float e = __expf(-2.0f * x);
    return __fdividef(1.0f - e, 1.0f + e);
}

// ---------------- phase 2: persistent recurrence (exact R5 version) ----------------
__global__ __launch_bounds__(256, 1) void recur_kernel(float* __restrict__ out)
{
    extern __shared__ __nv_bfloat16 smr[];
    __nv_bfloat16* WhiS = smr;
    __nv_bfloat16* WloS = smr + 32 * RSTR;
    __nv_bfloat16* hHiS = smr + 2 * 32 * RSTR;
    __nv_bfloat16* hLoS = smr + 3 * 32 * RSTR;
    float* gatesS = (float*)(smr + 4 * 32 * RSTR);  // [32][33]

    const int tid  = threadIdx.x;
    const int lane = tid & 31;
    const int warp = tid >> 5;
    const int q = blockIdx.x;          // 0..63
    const int d = blockIdx.y;          // 0..1
    const int j0 = q << 3;

    const __nv_bfloat16* Uh = g_Uhi + (size_t)d * 1048576;
    const __nv_bfloat16* Ul = g_Ulo + (size_t)d * 1048576;
    for (int e = tid; e < 4096; e += 256) {
        int r = e >> 7;
        int k = (e & 127) << 2;
        int grow = ((r >> 3) << 9) + j0 + (r & 7);
        size_t so = (size_t)grow * 512 + k;
        *(uint2*)&WhiS[r * RSTR + k] = *(const uint2*)(Uh + so);
        *(uint2*)&WloS[r * RSTR + k] = *(const uint2*)(Ul + so);
    }

    const uint32_t smb  = (uint32_t)__cvta_generic_to_shared(smr);
    const uint32_t WhiA = smb;
    const uint32_t WloA = smb + 32 * RSTR * 2;
    const uint32_t hHiA = smb + 2 * 32 * RSTR * 2;
    const uint32_t hLoA = smb + 3 * 32 * RSTR * 2;

    const int m0 = (warp & 1) << 4;
    const int n0 = (warp >> 1) << 3;
    const int l  = lane & 15;
    const uint32_t aRel = (uint32_t)(((m0 + l) * RSTR + ((lane >> 4) << 3)) * 2);
    const uint32_t bRel = (uint32_t)(((n0 + (l & 7)) * RSTR + ((l >> 3) << 3)) * 2);

    const int ab = tid >> 3, ajl = tid & 7;
    float c_reg = 0.0f;

    for (int s = 0; s < S_; s++) {
        const int t = d ? (S_ - 1 - s) : s;

        const uint32_t* hsrc = g_hpk[d][s & 1];
#pragma unroll
        for (int it = 0; it < 16; it++) {
            int e4 = tid + (it << 8);
            int b  = e4 >> 7;
            int k  = (e4 & 127) << 2;
            uint4 v = __ldcg((const uint4*)hsrc + e4);
            uint32_t hi01 = (v.x & 0xFFFFu) | (v.y << 16);
            uint32_t lo01 = (v.x >> 16)     | (v.y & 0xFFFF0000u);
            uint32_t hi23 = (v.z & 0xFFFFu) | (v.w << 16);
            uint32_t lo23 = (v.z >> 16)     | (v.w & 0xFFFF0000u);
            uint32_t off = (uint32_t)(b * RSTR + k);
            *(uint2*)&hHiS[off] = make_uint2(hi01, hi23);
            *(uint2*)&hLoS[off] = make_uint2(lo01, lo23);
        }

        const float* gpt = g_pre + (((size_t)(d * S_ + t) * B_ + ab) << 11) + j0 + ajl;
        float gp0 = __ldg(gpt);
        float gp1 = __ldg(gpt + 512);
        float gp2 = __ldg(gpt + 1024);
        float gp3 = __ldg(gpt + 1536);

        __syncthreads();

        float c4[4] = {0.f, 0.f, 0.f, 0.f};
#pragma unroll 8
        for (int ks = 0; ks < 32; ks++) {
            uint32_t koff = (uint32_t)(ks << 5);
            uint32_t ah[4], al[4], bh[2], bl[2];
            ldsm_x4(ah, hHiA + aRel + koff);
            ldsm_x4(al, hLoA + aRel + koff);
            ldsm_x2(bh, WhiA + bRel + koff);
            ldsm_x2(bl, WloA + bRel + koff);
            mma16816(c4, ah, bh);
            mma16816(c4, ah, bl);
            mma16816(c4, al, bh);
        }

        {
            int row = m0 + (lane >> 2);
            int col = n0 + ((lane & 3) << 1);
            gatesS[row * 33 + col]           = c4[0];
            gatesS[row * 33 + col + 1]       = c4[1];
            gatesS[(row + 8) * 33 + col]     = c4[2];
            gatesS[(row + 8) * 33 + col + 1] = c4[3];
        }
        __syncthreads();

        {
            const float* gb = gatesS + ab * 33;
            float i_s = sigm_(gb[ajl]      + gp0);
            float f_s = sigm_(gb[8 + ajl]  + gp1);
            float g_t = tanh_(gb[16 + ajl] + gp2);
            float o_s = sigm_(gb[24 + ajl] + gp3);
            c_reg = f_s * c_reg + i_s * g_t;
            float h = o_s * tanh_(c_reg);

            __nv_bfloat16 hh = __float2bfloat16(h);
            __nv_bfloat16 hl = __float2bfloat16(h - __bfloat162float(hh));
            uint32_t pk = ((uint32_t)__bfloat16_as_ushort(hl) << 16) |
                          (uint32_t)__bfloat16_as_ushort(hh);
            g_hpk[d][(s + 1) & 1][(ab << 9) + j0 + ajl] = pk;

            out[((size_t)(ab * S_ + t) << 10) + (d << 9) + j0 + ajl] = h;
            if (s == S_ - 1) {
                size_t fo = (size_t)(d * B_ + ab) * H_ + j0 + ajl;
                out[SH_OFF + fo] = h;
                out[SC_OFF + fo] = c_reg;
            }
        }
        __syncthreads();

        if (tid == 0) {
            __threadfence();
            atomicAdd(&g_bar[d], 1u);
            unsigned int target = 64u * (unsigned)(s + 1);
            volatile unsigned int* p = &g_bar[d];
            while (*p < target) __nanosleep(32);
            __threadfence();
        }
        __syncthreads();
    }
}

// ---------------- launch ----------------
extern "C" void kernel_launch(void* const* d_in, const int* in_sizes, int n_in,
                              void* d_out, int out_size) {
    const float* X     = (const float*)d_in[0];
    const float* Wih_f = (const float*)d_in[1];
    const float* Whh_f = (const float*)d_in[2];
    const float* bih_f = (const float*)d_in[3];
    const float* bhh_f = (const float*)d_in[4];
    const float* Wih_b = (const float*)d_in[5];
    const float* Whh_b = (const float*)d_in[6];
    const float* bih_b = (const float*)d_in[7];
    const float* bhh_b = (const float*)d_in[8];
    float* out = (float*)d_out;

    static const size_t rec_sh = (size_t)(4 * 32 * RSTR) * 2 + 32 * 33 * 4; // 137344
    static const size_t gem_sh = 2 * XST;                                    // 110592
    cudaFuncSetAttribute(recur_kernel, cudaFuncAttributeMaxDynamicSharedMemorySize, (int)rec_sh);
    cudaFuncSetAttribute(xgemm_mma,    cudaFuncAttributeMaxDynamicSharedMemorySize, (int)gem_sh);

    init_kernel<<<(2 * 2 * B_ * H_ + 255) / 256, 256>>>();
    prep_kernel<<<(2097152 + 4 * 262144 + 255) / 256, 256>>>(X, Wih_f, Wih_b, Whh_f, Whh_b);
    xgemm_mma<<<dim3(G4_ / 64, (B_ * S_) / 128, 2), 256, gem_sh>>>(bih_f, bhh_f, bih_b, bhh_b);
    recur_kernel<<<dim3(64, 2), 256, rec_sh>>>(out);
}